// round 10
// baseline (speedup 1.0000x reference)
#include <cuda_runtime.h>
#include <cuda_bf16.h>
#include <math.h>
#include <stdint.h>

#define NN 50000
#define EE 500000
#define ESLN 550000   // EE + NN (edges with self loops)
#define FIN 128
#define HC 256
#define CH 128
#define NCLASS 10
#define NB0 49        // ceil(NN/1024)

// ---------------- scratch (static __device__ globals; no allocation) -------
__device__ int   g_src[ESLN];
__device__ int   g_dst[ESLN];
__device__ int   g_cnt[NN];
__device__ int   g_cursor[NN];
__device__ int   g_rowptr1[NN + 1];
__device__ int   g_perm1[ESLN];
__device__ float g_XLR[(size_t)NN * 512];   // [N,512]: 0..255 = xl, 256..511 = xr
__device__ __nv_bfloat16 g_Ahi[(size_t)NN * HC];
__device__ __nv_bfloat16 g_Alo[(size_t)NN * HC];
__device__ __nv_bfloat16 g_Whi[640 * 512];  // layer0 rows 0-127, l1 128-383, l2 384-639
__device__ __nv_bfloat16 g_Wlo[640 * 512];
__device__ float g_partial[256];
__device__ float g_wmean;
__device__ int   g_bsum[64];

// ---------------- small utility kernels ------------------------------------
__global__ void zero_int_kernel(int* p, int n) {
    int i = blockIdx.x * blockDim.x + threadIdx.x;
    if (i < n) p[i] = 0;
}

// edge decode (int32/int64 robust) + self loops + dst histogram (fused).
__global__ void convert_edges_hist_kernel(const unsigned int* __restrict__ ei,
                                          int* __restrict__ src, int* __restrict__ dst,
                                          int* __restrict__ cnt) {
    __shared__ int s_is64;
    if (threadIdx.x == 0) {
        unsigned int acc = 0;
#pragma unroll
        for (int k = 0; k < 32; k++) acc |= ei[2 * k + 1];
        s_is64 = (acc == 0u) ? 1 : 0;
    }
    __syncthreads();
    int is64 = s_is64;
    int i = blockIdx.x * blockDim.x + threadIdx.x;
    if (i >= ESLN) return;
    int s, d;
    if (i < EE) {
        if (is64) {
            const long long* p = reinterpret_cast<const long long*>(ei);
            s = (int)p[i];
            d = (int)p[EE + i];
        } else {
            const int* p = reinterpret_cast<const int*>(ei);
            s = p[i];
            d = p[EE + i];
        }
    } else {
        s = d = i - EE;
    }
    src[i] = s;
    dst[i] = d;
    atomicAdd(&cnt[d], 1);
}

__global__ void mean_partial_kernel(const float* __restrict__ w) {
    __shared__ float s[256];
    float acc = 0.f;
    for (int i = blockIdx.x * 256 + threadIdx.x; i < EE; i += 256 * 256) acc += w[i];
    s[threadIdx.x] = acc;
    __syncthreads();
    for (int off = 128; off > 0; off >>= 1) {
        if (threadIdx.x < off) s[threadIdx.x] += s[threadIdx.x + off];
        __syncthreads();
    }
    if (threadIdx.x == 0) g_partial[blockIdx.x] = s[0];
}

__global__ void mean_final_kernel() {
    __shared__ float s[256];
    s[threadIdx.x] = g_partial[threadIdx.x];
    __syncthreads();
    for (int off = 128; off > 0; off >>= 1) {
        if (threadIdx.x < off) s[threadIdx.x] += s[threadIdx.x + off];
        __syncthreads();
    }
    if (threadIdx.x == 0) g_wmean = s[0] / (float)EE;
}

// ---- 3-phase scan ----
__global__ void scan_local_kernel(const int* __restrict__ cnt, int* __restrict__ rowptr) {
    __shared__ int s[1024];
    int t = threadIdx.x;
    int i = blockIdx.x * 1024 + t;
    int v = (i < NN) ? cnt[i] : 0;
    s[t] = v;
    __syncthreads();
    for (int off = 1; off < 1024; off <<= 1) {
        int x = s[t];
        int y = (t >= off) ? s[t - off] : 0;
        __syncthreads();
        s[t] = x + y;
        __syncthreads();
    }
    if (i < NN) rowptr[i] = s[t] - v;
    if (t == 1023) g_bsum[blockIdx.x] = s[1023];
}

__global__ void scan_bsum_kernel(int* __restrict__ rowptr) {
    __shared__ int s[64];
    int t = threadIdx.x;
    int v = (t < NB0) ? g_bsum[t] : 0;
    s[t] = v;
    __syncthreads();
    for (int off = 1; off < 64; off <<= 1) {
        int x = s[t];
        int y = (t >= off) ? s[t - off] : 0;
        __syncthreads();
        s[t] = x + y;
        __syncthreads();
    }
    if (t < NB0) g_bsum[t] = s[t] - v;
    if (t == 63) rowptr[NN] = s[63];
}

__global__ void scan_add_kernel(int* __restrict__ rowptr, int* __restrict__ cursor) {
    int i = blockIdx.x * 1024 + threadIdx.x;
    if (i < NN) {
        int r = rowptr[i] + g_bsum[blockIdx.x];
        rowptr[i] = r;
        cursor[i] = r;
    }
}

__global__ void scatter_kernel(const int* __restrict__ dst, int* __restrict__ cursor,
                               int* __restrict__ perm, int count) {
    int e = blockIdx.x * blockDim.x + threadIdx.x;
    if (e < count) {
        int p = atomicAdd(&cursor[dst[e]], 1);
        perm[p] = e;
    }
}

// ---------------- bf16 helpers ----------------------------------------------
__device__ __forceinline__ uint32_t pack_bf16(__nv_bfloat16 a, __nv_bfloat16 b) {
    __nv_bfloat162 t = __halves2bfloat162(a, b);
    return *reinterpret_cast<uint32_t*>(&t);
}

__device__ __forceinline__ void split_bf16(float x, __nv_bfloat16& h, __nv_bfloat16& l) {
    h = __float2bfloat16_rn(x);
    l = __float2bfloat16_rn(x - __bfloat162float(h));
}

__device__ __forceinline__ void mma_bf16(float* c, const uint32_t* a, uint32_t b0, uint32_t b1) {
    asm volatile(
        "mma.sync.aligned.m16n8k16.row.col.f32.bf16.bf16.f32 "
        "{%0,%1,%2,%3}, {%4,%5,%6,%7}, {%8,%9}, {%0,%1,%2,%3};"
        : "+f"(c[0]), "+f"(c[1]), "+f"(c[2]), "+f"(c[3])
        : "r"(a[0]), "r"(a[1]), "r"(a[2]), "r"(a[3]), "r"(b0), "r"(b1));
}

__device__ __forceinline__ void ldsm_x4(uint32_t* r, uint32_t saddr) {
    asm volatile("ldmatrix.sync.aligned.m8n8.x4.shared.b16 {%0,%1,%2,%3}, [%4];"
                 : "=r"(r[0]), "=r"(r[1]), "=r"(r[2]), "=r"(r[3]) : "r"(saddr));
}

__device__ __forceinline__ void ldsm_x4_t(uint32_t* r, uint32_t saddr) {
    asm volatile("ldmatrix.sync.aligned.m8n8.x4.trans.shared.b16 {%0,%1,%2,%3}, [%4];"
                 : "=r"(r[0]), "=r"(r[1]), "=r"(r[2]), "=r"(r[3]) : "r"(saddr));
}

__device__ __forceinline__ void cp_async16(uint32_t saddr, const void* g, int sz) {
    asm volatile("cp.async.cg.shared.global [%0], [%1], 16, %2;"
                 :: "r"(saddr), "l"(g), "r"(sz));
}

// ---------------- conversion kernels ----------------------------------------
__global__ void a_convert_kernel(const float* __restrict__ A,
                                 __nv_bfloat16* __restrict__ hi,
                                 __nv_bfloat16* __restrict__ lo, int total) {
    int i = (blockIdx.x * blockDim.x + threadIdx.x) * 4;
    if (i >= total) return;
    float4 v = *reinterpret_cast<const float4*>(A + i);
    __nv_bfloat16 h0, h1, h2, h3, l0, l1, l2, l3;
    split_bf16(v.x, h0, l0); split_bf16(v.y, h1, l1);
    split_bf16(v.z, h2, l2); split_bf16(v.w, h3, l3);
    *reinterpret_cast<uint2*>(hi + i) = make_uint2(pack_bf16(h0, h1), pack_bf16(h2, h3));
    *reinterpret_cast<uint2*>(lo + i) = make_uint2(pack_bf16(l0, l1), pack_bf16(l2, l3));
}

__global__ void w_convert_kernel(const float* __restrict__ Wl0, const float* __restrict__ Wr0,
                                 const float* __restrict__ Wl1, const float* __restrict__ Wr1,
                                 const float* __restrict__ Wl2, const float* __restrict__ Wr2) {
    int i = blockIdx.x * blockDim.x + threadIdx.x;
    if (i >= 640 * 512) return;
    int row = i >> 9, col = i & 511;
    const float *Wl, *Wr;
    int k;
    if (row < 128) { Wl = Wl0; Wr = Wr0; k = row; }
    else if (row < 384) { Wl = Wl1; Wr = Wr1; k = row - 128; }
    else { Wl = Wl2; Wr = Wr2; k = row - 384; }
    float v = (col < 256) ? Wl[k * 256 + col] : Wr[k * 256 + col - 256];
    __nv_bfloat16 h, l;
    split_bf16(v, h, l);
    g_Whi[i] = h;
    g_Wlo[i] = l;
}

// ---------------- GEMM: C[N,512] = A[N,K] @ W + bias -----------------------
// (unchanged from round 9: 3xBF16 hi/lo, cp.async+ldmatrix, issue-floor bound)
__global__ __launch_bounds__(256, 2) void gemm_bf16_ldsm_kernel(
    const __nv_bfloat16* __restrict__ Ahi, const __nv_bfloat16* __restrict__ Alo,
    int Mrows, int K,
    const __nv_bfloat16* __restrict__ Whi, const __nv_bfloat16* __restrict__ Wlo,
    const float* __restrict__ blv, const float* __restrict__ brv,
    float* __restrict__ Cmat) {
    extern __shared__ uint8_t smem[];
    uint32_t sbase = (uint32_t)__cvta_generic_to_shared(smem);
    const int bcol = blockIdx.x * 128;
    const int brow = blockIdx.y * 128;
    const int tid = threadIdx.x;
    const int lane = tid & 31;
    const int warp = tid >> 5;
    const int wm = warp >> 2;
    const int wn = warp & 3;

    float acc[4][4][4];
#pragma unroll
    for (int i = 0; i < 4; i++)
#pragma unroll
        for (int j = 0; j < 4; j++)
#pragma unroll
            for (int r = 0; r < 4; r++) acc[i][j][r] = 0.f;

    auto prefetch = [&](int kt, int soff) {
#pragma unroll
        for (int i = 0; i < 2; i++) {
            int c = tid + i * 256;
            int m = c >> 2, kc = c & 3;
            int grow = brow + m;
            int sz = (grow < Mrows) ? 16 : 0;
            uint32_t da = sbase + soff + (m * 4 + (kc ^ ((m >> 1) & 3))) * 16;
            size_t gofs = (size_t)grow * K + kt + kc * 8;
            cp_async16(da, Ahi + gofs, sz);
            cp_async16(da + 8192, Alo + gofs, sz);
        }
#pragma unroll
        for (int i = 0; i < 2; i++) {
            int c = tid + i * 256;
            int k = c >> 4, nc = c & 15;
            uint32_t db = sbase + soff + 16384 + (k * 16 + (nc ^ (k & 7))) * 16;
            size_t gofs = (size_t)(kt + k) * 512 + bcol + nc * 8;
            cp_async16(db, Whi + gofs, 16);
            cp_async16(db + 8192, Wlo + gofs, 16);
        }
        asm volatile("cp.async.commit_group;");
    };

    const int nk = K >> 5;
    prefetch(0, 0);
    asm volatile("cp.async.wait_group 0;");
    __syncthreads();

    const int lr = lane & 7;
    const int sel = lane >> 3;
    int buf = 0;
    for (int it = 0; it < nk; it++) {
        if (it + 1 < nk) prefetch((it + 1) << 5, (buf ^ 1) * 32768);
        int soff = buf * 32768;
#pragma unroll
        for (int s = 0; s < 2; s++) {
            uint32_t afrag[4][4], bfrag[2][4], b2frag[2][4];
#pragma unroll
            for (int t = 0; t < 4; t++) {
                int m = wm * 64 + t * 16 + lr + ((sel & 1) << 3);
                int kc = s * 2 + ((sel >> 1) & 1);
                uint32_t addr = sbase + soff + (m * 4 + (kc ^ ((m >> 1) & 3))) * 16;
                ldsm_x4(afrag[t], addr);
            }
#pragma unroll
            for (int j2 = 0; j2 < 2; j2++) {
                int k = s * 16 + ((sel & 1) << 3) + lr;
                int nt = wn * 4 + 2 * j2 + ((sel >> 1) & 1);
                uint32_t addr = sbase + soff + 16384 + (k * 16 + (nt ^ (k & 7))) * 16;
                ldsm_x4_t(bfrag[j2], addr);
            }
#pragma unroll
            for (int i = 0; i < 4; i++)
#pragma unroll
                for (int j = 0; j < 4; j++) {
                    const uint32_t* bp = &bfrag[j >> 1][(j & 1) * 2];
                    mma_bf16(acc[i][j], afrag[i], bp[0], bp[1]);
                }
#pragma unroll
            for (int j2 = 0; j2 < 2; j2++) {
                int k = s * 16 + ((sel & 1) << 3) + lr;
                int nt = wn * 4 + 2 * j2 + ((sel >> 1) & 1);
                uint32_t addr = sbase + soff + 16384 + (k * 16 + (nt ^ (k & 7))) * 16;
                ldsm_x4_t(b2frag[j2], addr + 8192);
            }
#pragma unroll
            for (int i = 0; i < 4; i++)
#pragma unroll
                for (int j = 0; j < 4; j++) {
                    const uint32_t* bp = &b2frag[j >> 1][(j & 1) * 2];
                    mma_bf16(acc[i][j], afrag[i], bp[0], bp[1]);
                }
#pragma unroll
            for (int t = 0; t < 4; t++) {
                int m = wm * 64 + t * 16 + lr + ((sel & 1) << 3);
                int kc = s * 2 + ((sel >> 1) & 1);
                uint32_t addr = sbase + soff + (m * 4 + (kc ^ ((m >> 1) & 3))) * 16;
                ldsm_x4(afrag[t], addr + 8192);
            }
#pragma unroll
            for (int i = 0; i < 4; i++)
#pragma unroll
                for (int j = 0; j < 4; j++) {
                    const uint32_t* bp = &bfrag[j >> 1][(j & 1) * 2];
                    mma_bf16(acc[i][j], afrag[i], bp[0], bp[1]);
                }
        }
        if (it + 1 < nk) asm volatile("cp.async.wait_group 0;");
        __syncthreads();
        buf ^= 1;
    }

    int r0 = lane >> 2;
    int c0 = (lane & 3) * 2;
#pragma unroll
    for (int j = 0; j < 4; j++) {
        int gcol = bcol + wn * 32 + j * 8 + c0;
        float b0v = (gcol < 256) ? blv[gcol] : brv[gcol - 256];
        float b1v = (gcol < 256) ? blv[gcol + 1] : brv[gcol + 1 - 256];
#pragma unroll
        for (int i = 0; i < 4; i++) {
            int grow = brow + wm * 64 + i * 16 + r0;
            if (grow < Mrows) {
                float2 v = make_float2(acc[i][j][0] + b0v, acc[i][j][1] + b1v);
                *reinterpret_cast<float2*>(Cmat + (size_t)grow * 512 + gcol) = v;
            }
            if (grow + 8 < Mrows) {
                float2 v = make_float2(acc[i][j][2] + b0v, acc[i][j][3] + b1v);
                *reinterpret_cast<float2*>(Cmat + (size_t)(grow + 8) * 512 + gcol) = v;
            }
        }
    }
}

// ---------------- fused GATv2 node kernel (both heads in one warp) ----------
// One warp per node. Lane l holds channels [4l,4l+4) of head0 AND head1.
// Last layer (fcW != null): classifier fused; H never touches memory.
__global__ __launch_bounds__(256) void gat_node_kernel(
    const float* __restrict__ XLR,
    const int* __restrict__ rowptr, const int* __restrict__ perm,
    const int* __restrict__ src, const float* __restrict__ wgt,
    const float* __restrict__ att, const float* __restrict__ We,
    const float* __restrict__ bias, int skipSelf,
    __nv_bfloat16* __restrict__ OutHi, __nv_bfloat16* __restrict__ OutLo,
    const float* __restrict__ fcW, const float* __restrict__ fcb,
    float* __restrict__ out) {
    int node = (blockIdx.x * blockDim.x + threadIdx.x) >> 5;
    if (node >= NN) return;
    int lane = threadIdx.x & 31;
    int b0 = lane * 4;        // head0 channels
    int b1 = 128 + lane * 4;  // head1 channels
    const float* xrow = XLR + (size_t)node * 512 + 256;
    const float4 xr0 = *reinterpret_cast<const float4*>(xrow + b0);
    const float4 xr1 = *reinterpret_cast<const float4*>(xrow + b1);
    const float4 av0 = *reinterpret_cast<const float4*>(att + b0);
    const float4 av1 = *reinterpret_cast<const float4*>(att + b1);
    const float4 wv0 = *reinterpret_cast<const float4*>(We + b0);
    const float4 wv1 = *reinterpret_cast<const float4*>(We + b1);
    float d0 = 0.f, d1 = 0.f;
    float4 ac0 = make_float4(0.f, 0.f, 0.f, 0.f);
    float4 ac1 = make_float4(0.f, 0.f, 0.f, 0.f);
    int i0 = rowptr[node], i1 = rowptr[node + 1];
    float wmean = g_wmean;
    int idx = i0;
#define EB(eV, pa, pb, xa, xb)                                                 \
    {                                                                          \
        int s_ = src[eV];                                                      \
        float ea_ = (eV < EE) ? __ldg(wgt + eV) : wmean;                       \
        const float* xp_ = XLR + (size_t)s_ * 512;                             \
        xa = *reinterpret_cast<const float4*>(xp_ + b0);                       \
        xb = *reinterpret_cast<const float4*>(xp_ + b1);                       \
        float q0 = xa.x + xr0.x + ea_ * wv0.x;                                 \
        float q1 = xa.y + xr0.y + ea_ * wv0.y;                                 \
        float q2 = xa.z + xr0.z + ea_ * wv0.z;                                 \
        float q3 = xa.w + xr0.w + ea_ * wv0.w;                                 \
        float r0_ = xb.x + xr1.x + ea_ * wv1.x;                                \
        float r1_ = xb.y + xr1.y + ea_ * wv1.y;                                \
        float r2_ = xb.z + xr1.z + ea_ * wv1.z;                                \
        float r3_ = xb.w + xr1.w + ea_ * wv1.w;                                \
        q0 = q0 > 0.f ? q0 : 0.2f * q0; q1 = q1 > 0.f ? q1 : 0.2f * q1;        \
        q2 = q2 > 0.f ? q2 : 0.2f * q2; q3 = q3 > 0.f ? q3 : 0.2f * q3;        \
        r0_ = r0_ > 0.f ? r0_ : 0.2f * r0_; r1_ = r1_ > 0.f ? r1_ : 0.2f * r1_;\
        r2_ = r2_ > 0.f ? r2_ : 0.2f * r2_; r3_ = r3_ > 0.f ? r3_ : 0.2f * r3_;\
        pa = q0 * av0.x + q1 * av0.y + q2 * av0.z + q3 * av0.w;                \
        pb = r0_ * av1.x + r1_ * av1.y + r2_ * av1.z + r3_ * av1.w;            \
    }
    for (; idx + 2 <= i1; idx += 2) {
        int e0 = perm[idx], e1 = perm[idx + 1];
        float pa0, pb0, pa1, pb1;
        float4 xa0, xb0, xa1, xb1;
        EB(e0, pa0, pb0, xa0, xb0);
        EB(e1, pa1, pb1, xa1, xb1);
#pragma unroll
        for (int off = 16; off >= 1; off >>= 1) {
            pa0 += __shfl_xor_sync(0xffffffffu, pa0, off);
            pb0 += __shfl_xor_sync(0xffffffffu, pb0, off);
            pa1 += __shfl_xor_sync(0xffffffffu, pa1, off);
            pb1 += __shfl_xor_sync(0xffffffffu, pb1, off);
        }
        float m0 = (skipSelf && e0 >= EE) ? 0.f : 1.f;
        float m1 = (skipSelf && e1 >= EE) ? 0.f : 1.f;
        float ea0 = __expf(pa0) * m0, eb0 = __expf(pb0) * m0;
        float ea1 = __expf(pa1) * m1, eb1 = __expf(pb1) * m1;
        d0 += ea0 + ea1;
        d1 += eb0 + eb1;
        ac0.x += ea0 * xa0.x + ea1 * xa1.x;
        ac0.y += ea0 * xa0.y + ea1 * xa1.y;
        ac0.z += ea0 * xa0.z + ea1 * xa1.z;
        ac0.w += ea0 * xa0.w + ea1 * xa1.w;
        ac1.x += eb0 * xb0.x + eb1 * xb1.x;
        ac1.y += eb0 * xb0.y + eb1 * xb1.y;
        ac1.z += eb0 * xb0.z + eb1 * xb1.z;
        ac1.w += eb0 * xb0.w + eb1 * xb1.w;
    }
    if (idx < i1) {
        int e = perm[idx];
        float pa, pb;
        float4 xa, xb;
        EB(e, pa, pb, xa, xb);
#pragma unroll
        for (int off = 16; off >= 1; off >>= 1) {
            pa += __shfl_xor_sync(0xffffffffu, pa, off);
            pb += __shfl_xor_sync(0xffffffffu, pb, off);
        }
        float m = (skipSelf && e >= EE) ? 0.f : 1.f;
        float ea = __expf(pa) * m, eb = __expf(pb) * m;
        d0 += ea; d1 += eb;
        ac0.x += ea * xa.x; ac0.y += ea * xa.y; ac0.z += ea * xa.z; ac0.w += ea * xa.w;
        ac1.x += eb * xb.x; ac1.y += eb * xb.y; ac1.z += eb * xb.z; ac1.w += eb * xb.w;
    }
#undef EB
    float iv0 = (d0 > 0.f) ? 1.f / (d0 + 1e-16f) : 0.f;
    float iv1 = (d1 > 0.f) ? 1.f / (d1 + 1e-16f) : 0.f;
    const float4 bv0 = *reinterpret_cast<const float4*>(bias + b0);
    const float4 bv1 = *reinterpret_cast<const float4*>(bias + b1);
    float o0 = ac0.x * iv0 + bv0.x, o1 = ac0.y * iv0 + bv0.y;
    float o2 = ac0.z * iv0 + bv0.z, o3 = ac0.w * iv0 + bv0.w;
    float o4 = ac1.x * iv1 + bv1.x, o5 = ac1.y * iv1 + bv1.y;
    float o6 = ac1.z * iv1 + bv1.z, o7 = ac1.w * iv1 + bv1.w;
    o0 = o0 > 0.f ? o0 : expm1f(o0); o1 = o1 > 0.f ? o1 : expm1f(o1);
    o2 = o2 > 0.f ? o2 : expm1f(o2); o3 = o3 > 0.f ? o3 : expm1f(o3);
    o4 = o4 > 0.f ? o4 : expm1f(o4); o5 = o5 > 0.f ? o5 : expm1f(o5);
    o6 = o6 > 0.f ? o6 : expm1f(o6); o7 = o7 > 0.f ? o7 : expm1f(o7);
    if (fcW) {
        // fused classifier: each lane holds 8 channels of the H row
        float fa[NCLASS];
#pragma unroll
        for (int k = 0; k < NCLASS; k++) fa[k] = 0.f;
        float ov[8] = {o0, o1, o2, o3, o4, o5, o6, o7};
#pragma unroll
        for (int j = 0; j < 8; j++) {
            int ch = (j < 4) ? (b0 + j) : (b1 + j - 4);
            const float* wr = fcW + (size_t)ch * NCLASS;
#pragma unroll
            for (int k = 0; k < NCLASS; k++) fa[k] += ov[j] * __ldg(wr + k);
        }
#pragma unroll
        for (int k = 0; k < NCLASS; k++) {
#pragma unroll
            for (int off = 16; off >= 1; off >>= 1)
                fa[k] += __shfl_xor_sync(0xffffffffu, fa[k], off);
        }
        if (lane == 0) {
#pragma unroll
            for (int k = 0; k < NCLASS; k++)
                out[(size_t)node * NCLASS + k] = fa[k] + fcb[k];
        }
    } else {
        __nv_bfloat16 h0, h1, h2, h3, l0, l1, l2, l3;
        size_t ofs = (size_t)node * HC;
        split_bf16(o0, h0, l0); split_bf16(o1, h1, l1);
        split_bf16(o2, h2, l2); split_bf16(o3, h3, l3);
        *reinterpret_cast<uint2*>(OutHi + ofs + b0) = make_uint2(pack_bf16(h0, h1), pack_bf16(h2, h3));
        *reinterpret_cast<uint2*>(OutLo + ofs + b0) = make_uint2(pack_bf16(l0, l1), pack_bf16(l2, l3));
        split_bf16(o4, h0, l0); split_bf16(o5, h1, l1);
        split_bf16(o6, h2, l2); split_bf16(o7, h3, l3);
        *reinterpret_cast<uint2*>(OutHi + ofs + b1) = make_uint2(pack_bf16(h0, h1), pack_bf16(h2, h3));
        *reinterpret_cast<uint2*>(OutLo + ofs + b1) = make_uint2(pack_bf16(l0, l1), pack_bf16(l2, l3));
    }
}

// ---------------- launch -----------------------------------------------------
extern "C" void kernel_launch(void* const* d_in, const int* in_sizes, int n_in,
                              void* d_out, int out_size) {
    const float* x = (const float*)d_in[0];
    const void* ei = d_in[1];
    const float* wgt = (const float*)d_in[2];
    const float *Wl[3], *bl[3], *Wr[3], *br[3], *We[3], *att[3], *bb[3];
    for (int i = 0; i < 3; i++) {
        int bse = 3 + 7 * i;
        Wl[i] = (const float*)d_in[bse + 0];
        bl[i] = (const float*)d_in[bse + 1];
        Wr[i] = (const float*)d_in[bse + 2];
        br[i] = (const float*)d_in[bse + 3];
        We[i] = (const float*)d_in[bse + 4];
        att[i] = (const float*)d_in[bse + 5];
        bb[i] = (const float*)d_in[bse + 6];
    }
    const float* fcW = (const float*)d_in[24];
    const float* fcb = (const float*)d_in[25];
    float* out = (float*)d_out;

    int *psrc, *pdst, *pcnt, *pcursor, *prow1, *pperm1;
    float* pXLR;
    __nv_bfloat16 *pAhi, *pAlo, *pWhi, *pWlo;
    cudaGetSymbolAddress((void**)&psrc, g_src);
    cudaGetSymbolAddress((void**)&pdst, g_dst);
    cudaGetSymbolAddress((void**)&pcnt, g_cnt);
    cudaGetSymbolAddress((void**)&pcursor, g_cursor);
    cudaGetSymbolAddress((void**)&prow1, g_rowptr1);
    cudaGetSymbolAddress((void**)&pperm1, g_perm1);
    cudaGetSymbolAddress((void**)&pXLR, g_XLR);
    cudaGetSymbolAddress((void**)&pAhi, g_Ahi);
    cudaGetSymbolAddress((void**)&pAlo, g_Alo);
    cudaGetSymbolAddress((void**)&pWhi, g_Whi);
    cudaGetSymbolAddress((void**)&pWlo, g_Wlo);

    cudaFuncSetAttribute(gemm_bf16_ldsm_kernel,
                         cudaFuncAttributeMaxDynamicSharedMemorySize, 65536);

    // prep: zero counts, then fused decode+selfloops+hist; weight mean
    zero_int_kernel<<<(NN + 255) / 256, 256>>>(pcnt, NN);
    convert_edges_hist_kernel<<<(ESLN + 255) / 256, 256>>>((const unsigned int*)ei,
                                                           psrc, pdst, pcnt);
    mean_partial_kernel<<<256, 256>>>(wgt);
    mean_final_kernel<<<1, 256>>>();

    // CSR (with self loops); layer 0 masks self loops at runtime
    scan_local_kernel<<<NB0, 1024>>>(pcnt, prow1);
    scan_bsum_kernel<<<1, 64>>>(prow1);
    scan_add_kernel<<<NB0, 1024>>>(prow1, pcursor);
    scatter_kernel<<<(ESLN + 255) / 256, 256>>>(pdst, pcursor, pperm1, ESLN);

    // weights -> bf16 hi/lo; x -> bf16 hi/lo
    w_convert_kernel<<<(640 * 512 + 255) / 256, 256>>>(Wl[0], Wr[0], Wl[1], Wr[1], Wl[2], Wr[2]);
    a_convert_kernel<<<(NN * FIN / 4 + 255) / 256, 256>>>(x, pAhi, pAlo, NN * FIN);

    dim3 ggrid(4, (NN + 127) / 128);
    int node_blocks = (NN * 32 + 255) / 256;  // one warp per node (both heads)

    // Layer 0 (mask self loops)
    gemm_bf16_ldsm_kernel<<<ggrid, 256, 65536>>>(pAhi, pAlo, NN, FIN,
                                                 pWhi, pWlo, bl[0], br[0], pXLR);
    gat_node_kernel<<<node_blocks, 256>>>(pXLR, prow1, pperm1, psrc, wgt,
                                          att[0], We[0], bb[0], 1,
                                          pAhi, pAlo, nullptr, nullptr, nullptr);
    // Layer 1
    gemm_bf16_ldsm_kernel<<<ggrid, 256, 65536>>>(pAhi, pAlo, NN, HC,
                                                 pWhi + 128 * 512, pWlo + 128 * 512,
                                                 bl[1], br[1], pXLR);
    gat_node_kernel<<<node_blocks, 256>>>(pXLR, prow1, pperm1, psrc, wgt,
                                          att[1], We[1], bb[1], 0,
                                          pAhi, pAlo, nullptr, nullptr, nullptr);
    // Layer 2 + fused classifier
    gemm_bf16_ldsm_kernel<<<ggrid, 256, 65536>>>(pAhi, pAlo, NN, HC,
                                                 pWhi + 384 * 512, pWlo + 384 * 512,
                                                 bl[2], br[2], pXLR);
    gat_node_kernel<<<node_blocks, 256>>>(pXLR, prow1, pperm1, psrc, wgt,
                                          att[2], We[2], bb[2], 0,
                                          nullptr, nullptr, fcW, fcb, out);
}